// round 1
// baseline (speedup 1.0000x reference)
#include <cuda_runtime.h>
#include <math.h>
#include <stdint.h>

// Problem constants
#define BSZ   8
#define TLEN  2048
#define CDIM  1024
#define HDIM  256
#define MTOT  (BSZ * TLEN)        // 16384

// Scratch for q, k, v projections (fp32) — __device__ globals (no allocs allowed)
__device__ float g_q[(size_t)MTOT * HDIM];
__device__ float g_k[(size_t)MTOT * HDIM];
__device__ float g_v[(size_t)MTOT * HDIM];

// ============================================================================
// Projection GEMM:  Out = X @ W   (X: [MTOT, CDIM], W: [CDIM, HDIM])
// Tiles: BM=64, BN=64, BK=16, 256 threads, 4x4 per thread.
// grid = (HDIM/64, MTOT/64, 3)  — z selects Wq/Wk/Wv.
// ============================================================================
#define PBM 64
#define PBN 64
#define PBK 16

__global__ __launch_bounds__(256) void proj_kernel(
    const float* __restrict__ x,
    const float* __restrict__ Wq,
    const float* __restrict__ Wk,
    const float* __restrict__ Wv)
{
    __shared__ __align__(16) float As[PBK][68];  // x tile, transposed [k][m], pad 4
    __shared__ __align__(16) float Bs[PBK][68];  // W tile [k][n], pad 4

    const int z = blockIdx.z;
    const float* __restrict__ W = (z == 0) ? Wq : ((z == 1) ? Wk : Wv);
    float* __restrict__ Out = (z == 0) ? g_q : ((z == 1) ? g_k : g_v);

    const int m0 = blockIdx.y * PBM;
    const int n0 = blockIdx.x * PBN;
    const int tid = threadIdx.x;
    const int tx = tid & 15;        // 0..15 -> output cols 4*tx..4*tx+3
    const int ty = tid >> 4;        // 0..15 -> output rows 4*ty..4*ty+3

    // load mapping
    const int lrow = tid >> 2;      // 0..63 (x row in tile)
    const int lkq  = tid & 3;       // 0..3  (float4 chunk of 16 k's)
    const int wrow = tid >> 4;      // 0..15 (k row of W tile)
    const int wnq  = tid & 15;      // 0..15 (float4 col)

    float acc[4][4] = {};

    for (int k0 = 0; k0 < CDIM; k0 += PBK) {
        float4 xv = *(const float4*)&x[(size_t)(m0 + lrow) * CDIM + k0 + 4 * lkq];
        float4 wv = *(const float4*)&W[(size_t)(k0 + wrow) * HDIM + n0 + 4 * wnq];
        __syncthreads();
        As[4 * lkq + 0][lrow] = xv.x;
        As[4 * lkq + 1][lrow] = xv.y;
        As[4 * lkq + 2][lrow] = xv.z;
        As[4 * lkq + 3][lrow] = xv.w;
        *(float4*)&Bs[wrow][4 * wnq] = wv;
        __syncthreads();

        #pragma unroll
        for (int k = 0; k < PBK; k++) {
            float4 a = *(const float4*)&As[k][4 * ty];
            float4 b = *(const float4*)&Bs[k][4 * tx];
            acc[0][0] = fmaf(a.x, b.x, acc[0][0]);
            acc[0][1] = fmaf(a.x, b.y, acc[0][1]);
            acc[0][2] = fmaf(a.x, b.z, acc[0][2]);
            acc[0][3] = fmaf(a.x, b.w, acc[0][3]);
            acc[1][0] = fmaf(a.y, b.x, acc[1][0]);
            acc[1][1] = fmaf(a.y, b.y, acc[1][1]);
            acc[1][2] = fmaf(a.y, b.z, acc[1][2]);
            acc[1][3] = fmaf(a.y, b.w, acc[1][3]);
            acc[2][0] = fmaf(a.z, b.x, acc[2][0]);
            acc[2][1] = fmaf(a.z, b.y, acc[2][1]);
            acc[2][2] = fmaf(a.z, b.z, acc[2][2]);
            acc[2][3] = fmaf(a.z, b.w, acc[2][3]);
            acc[3][0] = fmaf(a.w, b.x, acc[3][0]);
            acc[3][1] = fmaf(a.w, b.y, acc[3][1]);
            acc[3][2] = fmaf(a.w, b.z, acc[3][2]);
            acc[3][3] = fmaf(a.w, b.w, acc[3][3]);
        }
    }

    #pragma unroll
    for (int r = 0; r < 4; r++) {
        float4 o = make_float4(acc[r][0], acc[r][1], acc[r][2], acc[r][3]);
        *(float4*)&Out[(size_t)(m0 + 4 * ty + r) * HDIM + n0 + 4 * tx] = o;
    }
}

// ============================================================================
// Flash attention, fp32.
// One CTA per (batch, 64-query block). 256 threads as 16x16 (ty rows, tx cols).
// Q/K/V tiles in dynamic smem as float4 with XOR swizzle:
//   tile4[row*64 + (h4 ^ (row>>2))]
// P staged through padded smem [64][68].
// Softmax is online (flash); scale x16 folded into Q at load.
// ============================================================================
#define ABM 64
#define ABN 64
#define NH4 (HDIM / 4)   // 64 float4 per row
#define PS_LD 68         // P row stride (floats)

// dynamic smem: Qs(4096 f4) + Ks(4096) + Vs(4096) + Ps(64*68 floats)
#define SMEM_F4_TILES (3 * ABM * NH4)
#define ATTN_SMEM_BYTES (SMEM_F4_TILES * 16 + ABM * PS_LD * 4)

__device__ __forceinline__ void load_tile_swz(float4* __restrict__ dst,
                                              const float* __restrict__ src,
                                              float scale)
{
    const int tid = threadIdx.x;
    #pragma unroll
    for (int p = 0; p < 16; p++) {
        int idx = p * 256 + tid;
        int row = idx >> 6;          // 0..63
        int h4  = idx & 63;          // 0..63
        float4 v = *(const float4*)(src + (size_t)row * HDIM + 4 * h4);
        v.x *= scale; v.y *= scale; v.z *= scale; v.w *= scale;
        dst[row * NH4 + (h4 ^ (row >> 2))] = v;
    }
}

__global__ __launch_bounds__(256, 1) void attn_kernel(
    float* __restrict__ out)
{
    extern __shared__ __align__(16) float4 smem[];
    float4* Qs = smem;
    float4* Ks = smem + ABM * NH4;
    float4* Vs = smem + 2 * ABM * NH4;
    float*  Ps = (float*)(smem + SMEM_F4_TILES);   // [64][68]

    const int tid = threadIdx.x;
    const int tx = tid & 15;
    const int ty = tid >> 4;

    // heavy (large qb) blocks first
    const int bid = blockIdx.x;
    const int qb = (TLEN / ABM - 1) - (bid >> 3);   // 31..0
    const int b  = bid & 7;
    const int q0 = qb * ABM;

    const float* __restrict__ qbase = g_q + ((size_t)b * TLEN + q0) * HDIM;
    const float* __restrict__ kbase = g_k + (size_t)b * TLEN * HDIM;
    const float* __restrict__ vbase = g_v + (size_t)b * TLEN * HDIM;

    // load Q once, fold in the x16 scale (reference multiplies wei by sqrt(H)=16)
    load_tile_swz(Qs, qbase, 16.0f);

    float4 O[4][4];
    #pragma unroll
    for (int r = 0; r < 4; r++)
        #pragma unroll
        for (int g = 0; g < 4; g++)
            O[r][g] = make_float4(0.f, 0.f, 0.f, 0.f);

    float m_i[4], l_i[4];
    #pragma unroll
    for (int r = 0; r < 4; r++) { m_i[r] = -INFINITY; l_i[r] = 0.f; }

    for (int kb = 0; kb <= qb; kb++) {
        const int k0 = kb * ABN;
        __syncthreads();   // previous iter done reading Ks/Vs/Ps
        load_tile_swz(Ks, kbase + (size_t)k0 * HDIM, 1.0f);
        load_tile_swz(Vs, vbase + (size_t)k0 * HDIM, 1.0f);
        __syncthreads();

        // ---- S = Q K^T (64x64 tile; thread owns rows 4ty+r, cols 4tx+c) ----
        float S[4][4] = {};
        #pragma unroll 8
        for (int h4 = 0; h4 < NH4; h4++) {
            float4 a[4], bv[4];
            #pragma unroll
            for (int r = 0; r < 4; r++) a[r] = Qs[(4 * ty + r) * NH4 + (h4 ^ ty)];
            #pragma unroll
            for (int c = 0; c < 4; c++) bv[c] = Ks[(4 * tx + c) * NH4 + (h4 ^ tx)];
            #pragma unroll
            for (int r = 0; r < 4; r++)
                #pragma unroll
                for (int c = 0; c < 4; c++) {
                    S[r][c] = fmaf(a[r].x, bv[c].x, S[r][c]);
                    S[r][c] = fmaf(a[r].y, bv[c].y, S[r][c]);
                    S[r][c] = fmaf(a[r].z, bv[c].z, S[r][c]);
                    S[r][c] = fmaf(a[r].w, bv[c].w, S[r][c]);
                }
        }

        // causal mask on diagonal block (q0 == k0 there, so local compare works)
        if (kb == qb) {
            #pragma unroll
            for (int r = 0; r < 4; r++)
                #pragma unroll
                for (int c = 0; c < 4; c++)
                    if (4 * tx + c > 4 * ty + r) S[r][c] = -INFINITY;
        }

        // ---- online softmax per row (row stats shared across 16 tx lanes) ----
        #pragma unroll
        for (int r = 0; r < 4; r++) {
            float mloc = fmaxf(fmaxf(S[r][0], S[r][1]), fmaxf(S[r][2], S[r][3]));
            #pragma unroll
            for (int o = 8; o >= 1; o >>= 1)
                mloc = fmaxf(mloc, __shfl_xor_sync(0xffffffffu, mloc, o, 16));
            float m_new = fmaxf(m_i[r], mloc);
            float alpha = __expf(m_i[r] - m_new);
            float psum = 0.f;
            #pragma unroll
            for (int c = 0; c < 4; c++) {
                float p = __expf(S[r][c] - m_new);
                S[r][c] = p;
                psum += p;
            }
            #pragma unroll
            for (int o = 8; o >= 1; o >>= 1)
                psum += __shfl_xor_sync(0xffffffffu, psum, o, 16);
            l_i[r] = l_i[r] * alpha + psum;
            m_i[r] = m_new;
            #pragma unroll
            for (int g = 0; g < 4; g++) {
                O[r][g].x *= alpha; O[r][g].y *= alpha;
                O[r][g].z *= alpha; O[r][g].w *= alpha;
            }
            // stage P
            float4 pr = make_float4(S[r][0], S[r][1], S[r][2], S[r][3]);
            *(float4*)&Ps[(4 * ty + r) * PS_LD + 4 * tx] = pr;
        }
        __syncthreads();

        // ---- O += P @ V (thread owns rows 4ty+r, f4-cols tx+16g) ----
        #pragma unroll 4
        for (int j = 0; j < ABN; j++) {
            float p[4];
            #pragma unroll
            for (int r = 0; r < 4; r++) p[r] = Ps[(4 * ty + r) * PS_LD + j];
            float4 v[4];
            #pragma unroll
            for (int g = 0; g < 4; g++)
                v[g] = Vs[j * NH4 + ((tx + 16 * g) ^ (j >> 2))];
            #pragma unroll
            for (int r = 0; r < 4; r++)
                #pragma unroll
                for (int g = 0; g < 4; g++) {
                    O[r][g].x = fmaf(p[r], v[g].x, O[r][g].x);
                    O[r][g].y = fmaf(p[r], v[g].y, O[r][g].y);
                    O[r][g].z = fmaf(p[r], v[g].z, O[r][g].z);
                    O[r][g].w = fmaf(p[r], v[g].w, O[r][g].w);
                }
        }
    }

    // ---- epilogue: O /= l, write out ----
    float* __restrict__ outp = out + ((size_t)b * TLEN + q0) * HDIM;
    #pragma unroll
    for (int r = 0; r < 4; r++) {
        float inv = 1.0f / l_i[r];
        #pragma unroll
        for (int g = 0; g < 4; g++) {
            float4 o = O[r][g];
            o.x *= inv; o.y *= inv; o.z *= inv; o.w *= inv;
            *(float4*)&outp[(size_t)(4 * ty + r) * HDIM + 4 * (tx + 16 * g)] = o;
        }
    }
}

// ============================================================================
// Launch
// ============================================================================
extern "C" void kernel_launch(void* const* d_in, const int* in_sizes, int n_in,
                              void* d_out, int out_size)
{
    const float* x  = (const float*)d_in[0];
    const float* Wq = (const float*)d_in[1];
    const float* Wk = (const float*)d_in[2];
    const float* Wv = (const float*)d_in[3];
    float* out = (float*)d_out;

    (void)in_sizes; (void)n_in; (void)out_size;

    // Projections: q,k,v = x @ {Wq,Wk,Wv}
    dim3 pgrid(HDIM / PBN, MTOT / PBM, 3);
    proj_kernel<<<pgrid, 256>>>(x, Wq, Wk, Wv);

    // Flash attention
    cudaFuncSetAttribute(attn_kernel,
                         cudaFuncAttributeMaxDynamicSharedMemorySize,
                         ATTN_SMEM_BYTES);
    dim3 agrid((TLEN / ABM) * BSZ);  // 256 CTAs, heavy ones first
    attn_kernel<<<agrid, 256, ATTN_SMEM_BYTES>>>(out);
}

// round 4
// speedup vs baseline: 1.5234x; 1.5234x over previous
#include <cuda_runtime.h>
#include <cuda_bf16.h>
#include <math.h>
#include <stdint.h>

// Problem constants
#define BSZ   8
#define TLEN  2048
#define CDIM  1024
#define HDIM  256
#define MTOT  (BSZ * TLEN)        // 16384

// ============================================================================
// Device scratch (no allocs allowed)
// ============================================================================
__device__ float g_q[(size_t)MTOT * HDIM];
__device__ float g_k[(size_t)MTOT * HDIM];
__device__ float g_v[(size_t)MTOT * HDIM];
__device__ __nv_bfloat16 g_xhi[(size_t)MTOT * CDIM];   // 33.5 MB
__device__ __nv_bfloat16 g_xlo[(size_t)MTOT * CDIM];   // 33.5 MB
// W transposed+split: [z][sel][n=256][k=1024], z in {q,k,v}, sel in {hi,lo}
__device__ __nv_bfloat16 g_wt[(size_t)3 * 2 * HDIM * CDIM];

// ============================================================================
// Helpers (portable sm_80+ PTX only — target compiles as plain sm_100)
// ============================================================================
__device__ __forceinline__ uint32_t smem_u32(const void* p) {
    uint32_t a;
    asm("{ .reg .u64 t; cvta.to.shared.u64 t, %1; cvt.u32.u64 %0, t; }"
        : "=r"(a) : "l"(p));
    return a;
}

__device__ __forceinline__ void ldsm_x4(uint32_t* r, uint32_t addr) {
    asm volatile("ldmatrix.sync.aligned.m8n8.x4.shared.b16 {%0,%1,%2,%3}, [%4];"
                 : "=r"(r[0]), "=r"(r[1]), "=r"(r[2]), "=r"(r[3]) : "r"(addr));
}

__device__ __forceinline__ void mma_bf16(float* c, const uint32_t* a,
                                         uint32_t b0, uint32_t b1) {
    asm volatile(
        "mma.sync.aligned.m16n8k16.row.col.f32.bf16.bf16.f32 "
        "{%0,%1,%2,%3}, {%4,%5,%6,%7}, {%8,%9}, {%0,%1,%2,%3};"
        : "+f"(c[0]), "+f"(c[1]), "+f"(c[2]), "+f"(c[3])
        : "r"(a[0]), "r"(a[1]), "r"(a[2]), "r"(a[3]), "r"(b0), "r"(b1));
}

__device__ __forceinline__ void cp_async16(uint32_t dst, const void* src) {
    asm volatile("cp.async.cg.shared.global [%0], [%1], 16;"
                 :: "r"(dst), "l"(src));
}
#define CP_COMMIT() asm volatile("cp.async.commit_group;" ::: "memory")
#define CP_WAIT1()  asm volatile("cp.async.wait_group 1;" ::: "memory")
#define CP_WAIT0()  asm volatile("cp.async.wait_group 0;" ::: "memory")

// ============================================================================
// Prep: split x into bf16 hi/lo
// ============================================================================
__global__ __launch_bounds__(256) void split_x_kernel(const float* __restrict__ x)
{
    size_t i = ((size_t)blockIdx.x * 256 + threadIdx.x) * 4;
    float4 v = *(const float4*)(x + i);
    union { __nv_bfloat16 b[4]; uint2 u; } H, L;
    float f[4] = {v.x, v.y, v.z, v.w};
    #pragma unroll
    for (int j = 0; j < 4; j++) {
        __nv_bfloat16 h = __float2bfloat16(f[j]);
        H.b[j] = h;
        L.b[j] = __float2bfloat16(f[j] - __bfloat162float(h));
    }
    *(uint2*)&g_xhi[i] = H.u;
    *(uint2*)&g_xlo[i] = L.u;
}

// Prep: transpose + split W ([C,H] -> [n][k] hi/lo) for q,k,v
__global__ __launch_bounds__(256) void split_w_kernel(
    const float* __restrict__ Wq, const float* __restrict__ Wk,
    const float* __restrict__ Wv)
{
    int idx = blockIdx.x * 256 + threadIdx.x;          // < 3*262144
    int z = idx >> 18;
    int r = idx & 262143;
    int n = r & 255;
    int k = r >> 8;
    const float* W = (z == 0) ? Wq : ((z == 1) ? Wk : Wv);
    float v = W[(size_t)k * HDIM + n];
    __nv_bfloat16 h = __float2bfloat16(v);
    __nv_bfloat16 l = __float2bfloat16(v - __bfloat162float(h));
    size_t base = (size_t)z * 2 * HDIM * CDIM;
    g_wt[base + (size_t)n * CDIM + k] = h;
    g_wt[base + (size_t)HDIM * CDIM + (size_t)n * CDIM + k] = l;
}

// ============================================================================
// Projection GEMM via mma.sync bf16 (split: hi*hi + lo*hi + hi*lo).
// CTA tile M=128, N=128, K-chunk 64. 8 warps as 4(M)x2(N), warp tile 32x64.
// Double-buffered cp.async smem pipeline. grid = (MTOT/128, HDIM/128, 3).
// ============================================================================
#define PM 128
#define PN 128
#define PK 64
#define PKCH (CDIM / PK)       // 16 chunks per segment
#define PNCHUNK (3 * PKCH)     // 48

// smem: per buffer A(128x128B=16KB) + B(16KB); 2 buffers = 64KB
#define PA_OFF(b) ((b) * 32768)
#define PB_OFF(b) ((b) * 32768 + 16384)
#define PROJ_SMEM_BYTES 65536

__global__ __launch_bounds__(256, 1) void proj_mma_kernel()
{
    extern __shared__ __align__(16) char ps[];
    const uint32_t sbase = smem_u32(ps);
    const int tid  = threadIdx.x;
    const int lane = tid & 31;
    const int wid  = tid >> 5;
    const int wm   = wid & 3;          // warp M index (0..3)
    const int wn   = wid >> 2;         // warp N index (0..1)

    const int z  = blockIdx.z;
    const int m0 = blockIdx.x * PM;
    const int n0 = blockIdx.y * PN;

    const __nv_bfloat16* __restrict__ wtz = g_wt + (size_t)z * 2 * HDIM * CDIM;
    float* __restrict__ outp = (z == 0) ? g_q : ((z == 1) ? g_k : g_v);

    // loader mapping: 1024 16B-chunks per tile, 256 threads -> 4 iters
    const int lrow = tid >> 1;                 // 0..127 (two chunk-pairs/row? no:)
    // We map idx = it*256 + tid; row = idx>>3 (0..127), c = idx&7 (16B chunk).
    auto load_chunk = [&](int buf, int chunk) {
        const int seg = chunk >> 4;            // 0: hi*hi, 1: lo*hi, 2: hi*lo
        const int k0 = (chunk & 15) * PK;
        const __nv_bfloat16* __restrict__ asrc = (seg == 1) ? g_xlo : g_xhi;
        const __nv_bfloat16* __restrict__ bsrc =
            wtz + ((seg == 2) ? (size_t)HDIM * CDIM : 0);
        const uint32_t sa = sbase + PA_OFF(buf);
        const uint32_t sb = sbase + PB_OFF(buf);
        #pragma unroll
        for (int it = 0; it < 4; it++) {
            int idx = it * 256 + tid;
            int row = idx >> 3, c = idx & 7;
            uint32_t dst = sa + row * 128 + ((c ^ (row & 7)) << 4);
            cp_async16(dst, asrc + (size_t)(m0 + row) * CDIM + k0 + c * 8);
        }
        #pragma unroll
        for (int it = 0; it < 4; it++) {
            int idx = it * 256 + tid;
            int row = idx >> 3, c = idx & 7;
            uint32_t dst = sb + row * 128 + ((c ^ (row & 7)) << 4);
            cp_async16(dst, bsrc + (size_t)(n0 + row) * CDIM + k0 + c * 8);
        }
    };

    float acc[2][8][4];
    #pragma unroll
    for (int tm = 0; tm < 2; tm++)
        #pragma unroll
        for (int j = 0; j < 8; j++)
            #pragma unroll
            for (int e = 0; e < 4; e++) acc[tm][j][e] = 0.f;

    load_chunk(0, 0);
    CP_COMMIT();

    for (int i = 0; i < PNCHUNK; i++) {
        const int b = i & 1;
        if (i + 1 < PNCHUNK) {
            load_chunk(1 - b, i + 1);
            CP_COMMIT();
            CP_WAIT1();         // buffer b's group complete
        } else {
            CP_WAIT0();
        }
        __syncthreads();

        const uint32_t abase = sbase + PA_OFF(b);
        const uint32_t bbase = sbase + PB_OFF(b);
        #pragma unroll
        for (int k16 = 0; k16 < 4; k16++) {
            const int chunkSel = k16 * 2 + (lane >> 4);
            uint32_t a[2][4];
            #pragma unroll
            for (int tm = 0; tm < 2; tm++) {
                int row = wm * 32 + tm * 16 + (lane & 15);
                ldsm_x4(a[tm], abase + row * 128 + ((chunkSel ^ (row & 7)) << 4));
            }
            uint32_t bb[4][4];
            #pragma unroll
            for (int tn = 0; tn < 4; tn++) {
                int row = wn * 64 + tn * 16 + (lane & 15);
                ldsm_x4(bb[tn], bbase + row * 128 + ((chunkSel ^ (row & 7)) << 4));
            }
            #pragma unroll
            for (int tm = 0; tm < 2; tm++)
                #pragma unroll
                for (int tn = 0; tn < 4; tn++) {
                    mma_bf16(acc[tm][tn * 2 + 0], a[tm], bb[tn][0], bb[tn][2]);
                    mma_bf16(acc[tm][tn * 2 + 1], a[tm], bb[tn][1], bb[tn][3]);
                }
        }
        __syncthreads();
    }

    // ---- epilogue: c-frag -> fp32 global ----
    const int gr = lane >> 2;          // 0..7
    const int gc = lane & 3;           // 0..3
    #pragma unroll
    for (int tm = 0; tm < 2; tm++) {
        #pragma unroll
        for (int j = 0; j < 8; j++) {
            int r0  = m0 + wm * 32 + tm * 16 + gr;
            int col = n0 + wn * 64 + j * 8 + gc * 2;
            *(float2*)&outp[(size_t)r0 * HDIM + col] =
                make_float2(acc[tm][j][0], acc[tm][j][1]);
            *(float2*)&outp[(size_t)(r0 + 8) * HDIM + col] =
                make_float2(acc[tm][j][2], acc[tm][j][3]);
        }
    }
}

// ============================================================================
// Flash attention, fp32 (unchanged — proven at 556us)
// ============================================================================
#define ABM 64
#define ABN 64
#define NH4 (HDIM / 4)
#define PS_LD 68
#define SMEM_F4_TILES (3 * ABM * NH4)
#define ATTN_SMEM_BYTES (SMEM_F4_TILES * 16 + ABM * PS_LD * 4)

__device__ __forceinline__ void load_tile_swz(float4* __restrict__ dst,
                                              const float* __restrict__ src,
                                              float scale)
{
    const int tid = threadIdx.x;
    #pragma unroll
    for (int p = 0; p < 16; p++) {
        int idx = p * 256 + tid;
        int row = idx >> 6;
        int h4  = idx & 63;
        float4 v = *(const float4*)(src + (size_t)row * HDIM + 4 * h4);
        v.x *= scale; v.y *= scale; v.z *= scale; v.w *= scale;
        dst[row * NH4 + (h4 ^ (row >> 2))] = v;
    }
}

__global__ __launch_bounds__(256, 1) void attn_kernel(float* __restrict__ out)
{
    extern __shared__ __align__(16) float4 smem[];
    float4* Qs = smem;
    float4* Ks = smem + ABM * NH4;
    float4* Vs = smem + 2 * ABM * NH4;
    float*  Ps = (float*)(smem + SMEM_F4_TILES);

    const int tid = threadIdx.x;
    const int tx = tid & 15;
    const int ty = tid >> 4;

    const int bid = blockIdx.x;
    const int qb = (TLEN / ABM - 1) - (bid >> 3);
    const int b  = bid & 7;
    const int q0 = qb * ABM;

    const float* __restrict__ qbase = g_q + ((size_t)b * TLEN + q0) * HDIM;
    const float* __restrict__ kbase = g_k + (size_t)b * TLEN * HDIM;
    const float* __restrict__ vbase = g_v + (size_t)b * TLEN * HDIM;

    load_tile_swz(Qs, qbase, 16.0f);

    float4 O[4][4];
    #pragma unroll
    for (int r = 0; r < 4; r++)
        #pragma unroll
        for (int g = 0; g < 4; g++)
            O[r][g] = make_float4(0.f, 0.f, 0.f, 0.f);

    float m_i[4], l_i[4];
    #pragma unroll
    for (int r = 0; r < 4; r++) { m_i[r] = -INFINITY; l_i[r] = 0.f; }

    for (int kb = 0; kb <= qb; kb++) {
        const int k0 = kb * ABN;
        __syncthreads();
        load_tile_swz(Ks, kbase + (size_t)k0 * HDIM, 1.0f);
        load_tile_swz(Vs, vbase + (size_t)k0 * HDIM, 1.0f);
        __syncthreads();

        float S[4][4] = {};
        #pragma unroll 8
        for (int h4 = 0; h4 < NH4; h4++) {
            float4 a[4], bv[4];
            #pragma unroll
            for (int r = 0; r < 4; r++) a[r] = Qs[(4 * ty + r) * NH4 + (h4 ^ ty)];
            #pragma unroll
            for (int c = 0; c < 4; c++) bv[c] = Ks[(4 * tx + c) * NH4 + (h4 ^ tx)];
            #pragma unroll
            for (int r = 0; r < 4; r++)
                #pragma unroll
                for (int c = 0; c < 4; c++) {
                    S[r][c] = fmaf(a[r].x, bv[c].x, S[r][c]);
                    S[r][c] = fmaf(a[r].y, bv[c].y, S[r][c]);
                    S[r][c] = fmaf(a[r].z, bv[c].z, S[r][c]);
                    S[r][c] = fmaf(a[r].w, bv[c].w, S[r][c]);
                }
        }

        if (kb == qb) {
            #pragma unroll
            for (int r = 0; r < 4; r++)
                #pragma unroll
                for (int c = 0; c < 4; c++)
                    if (4 * tx + c > 4 * ty + r) S[r][c] = -INFINITY;
        }

        #pragma unroll
        for (int r = 0; r < 4; r++) {
            float mloc = fmaxf(fmaxf(S[r][0], S[r][1]), fmaxf(S[r][2], S[r][3]));
            #pragma unroll
            for (int o = 8; o >= 1; o >>= 1)
                mloc = fmaxf(mloc, __shfl_xor_sync(0xffffffffu, mloc, o, 16));
            float m_new = fmaxf(m_i[r], mloc);
            float alpha = __expf(m_i[r] - m_new);
            float psum = 0.f;
            #pragma unroll
            for (int c = 0; c < 4; c++) {
                float p = __expf(S[r][c] - m_new);
                S[r][c] = p;
                psum += p;
            }
            #pragma unroll
            for (int o = 8; o >= 1; o >>= 1)
                psum += __shfl_xor_sync(0xffffffffu, psum, o, 16);
            l_i[r] = l_i[r] * alpha + psum;
            m_i[r] = m_new;
            #pragma unroll
            for (int g = 0; g < 4; g++) {
                O[r][g].x *= alpha; O[r][g].y *= alpha;
                O[r][g].z *= alpha; O[r][g].w *= alpha;
            }
            float4 pr = make_float4(S[r][0], S[r][1], S[r][2], S[r][3]);
            *(float4*)&Ps[(4 * ty + r) * PS_LD + 4 * tx] = pr;
        }
        __syncthreads();

        #pragma unroll 4
        for (int j = 0; j < ABN; j++) {
            float p[4];
            #pragma unroll
            for (int r = 0; r < 4; r++) p[r] = Ps[(4 * ty + r) * PS_LD + j];
            float4 v[4];
            #pragma unroll
            for (int g = 0; g < 4; g++)
                v[g] = Vs[j * NH4 + ((tx + 16 * g) ^ (j >> 2))];
            #pragma unroll
            for (int r = 0; r < 4; r++)
                #pragma unroll
                for (int g = 0; g < 4; g++) {
                    O[r][g].x = fmaf(p[r], v[g].x, O[r][g].x);
                    O[r][g].y = fmaf(p[r], v[g].y, O[r][g].y);
                    O[r][g].z = fmaf(p[r], v[g].z, O[r][g].z);
                    O[r][g].w = fmaf(p[r], v[g].w, O[r][g].w);
                }
        }
    }

    float* __restrict__ outp = out + ((size_t)b * TLEN + q0) * HDIM;
    #pragma unroll
    for (int r = 0; r < 4; r++) {
        float inv = 1.0f / l_i[r];
        #pragma unroll
        for (int g = 0; g < 4; g++) {
            float4 o = O[r][g];
            o.x *= inv; o.y *= inv; o.z *= inv; o.w *= inv;
            *(float4*)&outp[(size_t)(4 * ty + r) * HDIM + 4 * (tx + 16 * g)] = o;
        }
    }
}

// ============================================================================
// Launch
// ============================================================================
extern "C" void kernel_launch(void* const* d_in, const int* in_sizes, int n_in,
                              void* d_out, int out_size)
{
    const float* x  = (const float*)d_in[0];
    const float* Wq = (const float*)d_in[1];
    const float* Wk = (const float*)d_in[2];
    const float* Wv = (const float*)d_in[3];
    float* out = (float*)d_out;
    (void)in_sizes; (void)n_in; (void)out_size;

    // Split inputs into bf16 hi/lo
    split_x_kernel<<<(size_t)MTOT * CDIM / (256 * 4), 256>>>(x);
    split_w_kernel<<<3 * CDIM * HDIM / 256, 256>>>(Wq, Wk, Wv);

    // mma.sync projections -> g_q, g_k, g_v (fp32)
    cudaFuncSetAttribute(proj_mma_kernel,
                         cudaFuncAttributeMaxDynamicSharedMemorySize,
                         PROJ_SMEM_BYTES);
    dim3 pgrid(MTOT / PM, HDIM / PN, 3);
    proj_mma_kernel<<<pgrid, 256, PROJ_SMEM_BYTES>>>();

    // Flash attention (fp32 FFMA)
    cudaFuncSetAttribute(attn_kernel,
                         cudaFuncAttributeMaxDynamicSharedMemorySize,
                         ATTN_SMEM_BYTES);
    dim3 agrid((TLEN / ABM) * BSZ);
    attn_kernel<<<agrid, 256, ATTN_SMEM_BYTES>>>(out);
}

// round 5
// speedup vs baseline: 2.3783x; 1.5612x over previous
#include <cuda_runtime.h>
#include <cuda_bf16.h>
#include <math.h>
#include <stdint.h>

// Problem constants
#define BSZ   8
#define TLEN  2048
#define CDIM  1024
#define HDIM  256
#define MTOT  (BSZ * TLEN)        // 16384

// ============================================================================
// Device scratch (no allocs allowed)
// ============================================================================
__device__ __nv_bfloat16 g_xhi[(size_t)MTOT * CDIM];   // 33.5 MB
__device__ __nv_bfloat16 g_xlo[(size_t)MTOT * CDIM];   // 33.5 MB
// W transposed+split: [z][sel][n=256][k=1024]
__device__ __nv_bfloat16 g_wt[(size_t)3 * 2 * HDIM * CDIM];
// q/k/v in bf16 hi/lo, [z][t][h]; q has x16 scale folded in
__device__ __nv_bfloat16 g_h[3][(size_t)MTOT * HDIM];
__device__ __nv_bfloat16 g_l[3][(size_t)MTOT * HDIM];

// ============================================================================
// Helpers (portable sm_80+ PTX only)
// ============================================================================
__device__ __forceinline__ uint32_t smem_u32(const void* p) {
    uint32_t a;
    asm("{ .reg .u64 t; cvta.to.shared.u64 t, %1; cvt.u32.u64 %0, t; }"
        : "=r"(a) : "l"(p));
    return a;
}

__device__ __forceinline__ void ldsm_x4(uint32_t* r, uint32_t addr) {
    asm volatile("ldmatrix.sync.aligned.m8n8.x4.shared.b16 {%0,%1,%2,%3}, [%4];"
                 : "=r"(r[0]), "=r"(r[1]), "=r"(r[2]), "=r"(r[3]) : "r"(addr));
}
__device__ __forceinline__ void ldsm_x4_t(uint32_t* r, uint32_t addr) {
    asm volatile("ldmatrix.sync.aligned.m8n8.x4.trans.shared.b16 {%0,%1,%2,%3}, [%4];"
                 : "=r"(r[0]), "=r"(r[1]), "=r"(r[2]), "=r"(r[3]) : "r"(addr));
}

__device__ __forceinline__ void mma_bf16(float* c, const uint32_t* a,
                                         uint32_t b0, uint32_t b1) {
    asm volatile(
        "mma.sync.aligned.m16n8k16.row.col.f32.bf16.bf16.f32 "
        "{%0,%1,%2,%3}, {%4,%5,%6,%7}, {%8,%9}, {%0,%1,%2,%3};"
        : "+f"(c[0]), "+f"(c[1]), "+f"(c[2]), "+f"(c[3])
        : "r"(a[0]), "r"(a[1]), "r"(a[2]), "r"(a[3]), "r"(b0), "r"(b1));
}

__device__ __forceinline__ void cp_async16(uint32_t dst, const void* src) {
    asm volatile("cp.async.cg.shared.global [%0], [%1], 16;"
                 :: "r"(dst), "l"(src));
}
#define CP_COMMIT() asm volatile("cp.async.commit_group;" ::: "memory")
#define CP_WAIT1()  asm volatile("cp.async.wait_group 1;" ::: "memory")
#define CP_WAIT0()  asm volatile("cp.async.wait_group 0;" ::: "memory")

__device__ __forceinline__ uint32_t pack_bf16(float a, float b) {
    __nv_bfloat16 ha = __float2bfloat16(a), hb = __float2bfloat16(b);
    uint32_t u = ((uint32_t)*(uint16_t*)&hb << 16) | (uint32_t)*(uint16_t*)&ha;
    return u;
}

// ============================================================================
// Prep: split x into bf16 hi/lo
// ============================================================================
__global__ __launch_bounds__(256) void split_x_kernel(const float* __restrict__ x)
{
    size_t i = ((size_t)blockIdx.x * 256 + threadIdx.x) * 4;
    float4 v = *(const float4*)(x + i);
    union { __nv_bfloat16 b[4]; uint2 u; } H, L;
    float f[4] = {v.x, v.y, v.z, v.w};
    #pragma unroll
    for (int j = 0; j < 4; j++) {
        __nv_bfloat16 h = __float2bfloat16(f[j]);
        H.b[j] = h;
        L.b[j] = __float2bfloat16(f[j] - __bfloat162float(h));
    }
    *(uint2*)&g_xhi[i] = H.u;
    *(uint2*)&g_xlo[i] = L.u;
}

__global__ __launch_bounds__(256) void split_w_kernel(
    const float* __restrict__ Wq, const float* __restrict__ Wk,
    const float* __restrict__ Wv)
{
    int idx = blockIdx.x * 256 + threadIdx.x;
    int z = idx >> 18;
    int r = idx & 262143;
    int n = r & 255;
    int k = r >> 8;
    const float* W = (z == 0) ? Wq : ((z == 1) ? Wk : Wv);
    float v = W[(size_t)k * HDIM + n];
    __nv_bfloat16 h = __float2bfloat16(v);
    __nv_bfloat16 l = __float2bfloat16(v - __bfloat162float(h));
    size_t base = (size_t)z * 2 * HDIM * CDIM;
    g_wt[base + (size_t)n * CDIM + k] = h;
    g_wt[base + (size_t)HDIM * CDIM + (size_t)n * CDIM + k] = l;
}

// ============================================================================
// Projection GEMM via mma.sync bf16 (hi*hi + lo*hi + hi*lo).
// Epilogue: write bf16 hi/lo q/k/v (q scaled x16 exactly).
// ============================================================================
#define PM 128
#define PN 128
#define PK 64
#define PNCHUNK (3 * (CDIM / PK))     // 48

#define PA_OFF(b) ((b) * 32768)
#define PB_OFF(b) ((b) * 32768 + 16384)
#define PROJ_SMEM_BYTES 65536

__global__ __launch_bounds__(256, 1) void proj_mma_kernel()
{
    extern __shared__ __align__(16) char ps[];
    const uint32_t sbase = smem_u32(ps);
    const int tid  = threadIdx.x;
    const int lane = tid & 31;
    const int wid  = tid >> 5;
    const int wm   = wid & 3;
    const int wn   = wid >> 2;

    const int z  = blockIdx.z;
    const int m0 = blockIdx.x * PM;
    const int n0 = blockIdx.y * PN;

    const __nv_bfloat16* __restrict__ wtz = g_wt + (size_t)z * 2 * HDIM * CDIM;

    auto load_chunk = [&](int buf, int chunk) {
        const int seg = chunk >> 4;
        const int k0 = (chunk & 15) * PK;
        const __nv_bfloat16* __restrict__ asrc = (seg == 1) ? g_xlo : g_xhi;
        const __nv_bfloat16* __restrict__ bsrc =
            wtz + ((seg == 2) ? (size_t)HDIM * CDIM : 0);
        const uint32_t sa = sbase + PA_OFF(buf);
        const uint32_t sb = sbase + PB_OFF(buf);
        #pragma unroll
        for (int it = 0; it < 4; it++) {
            int idx = it * 256 + tid;
            int row = idx >> 3, c = idx & 7;
            cp_async16(sa + row * 128 + ((c ^ (row & 7)) << 4),
                       asrc + (size_t)(m0 + row) * CDIM + k0 + c * 8);
        }
        #pragma unroll
        for (int it = 0; it < 4; it++) {
            int idx = it * 256 + tid;
            int row = idx >> 3, c = idx & 7;
            cp_async16(sb + row * 128 + ((c ^ (row & 7)) << 4),
                       bsrc + (size_t)(n0 + row) * CDIM + k0 + c * 8);
        }
    };

    float acc[2][8][4];
    #pragma unroll
    for (int tm = 0; tm < 2; tm++)
        #pragma unroll
        for (int j = 0; j < 8; j++)
            #pragma unroll
            for (int e = 0; e < 4; e++) acc[tm][j][e] = 0.f;

    load_chunk(0, 0);
    CP_COMMIT();

    for (int i = 0; i < PNCHUNK; i++) {
        const int b = i & 1;
        if (i + 1 < PNCHUNK) {
            load_chunk(1 - b, i + 1);
            CP_COMMIT();
            CP_WAIT1();
        } else {
            CP_WAIT0();
        }
        __syncthreads();

        const uint32_t abase = sbase + PA_OFF(b);
        const uint32_t bbase = sbase + PB_OFF(b);
        #pragma unroll
        for (int k16 = 0; k16 < 4; k16++) {
            const int chunkSel = k16 * 2 + (lane >> 4);
            uint32_t a[2][4];
            #pragma unroll
            for (int tm = 0; tm < 2; tm++) {
                int row = wm * 32 + tm * 16 + (lane & 15);
                ldsm_x4(a[tm], abase + row * 128 + ((chunkSel ^ (row & 7)) << 4));
            }
            uint32_t bb[4][4];
            #pragma unroll
            for (int tn = 0; tn < 4; tn++) {
                int row = wn * 64 + tn * 16 + (lane & 15);
                ldsm_x4(bb[tn], bbase + row * 128 + ((chunkSel ^ (row & 7)) << 4));
            }
            #pragma unroll
            for (int tm = 0; tm < 2; tm++)
                #pragma unroll
                for (int tn = 0; tn < 4; tn++) {
                    mma_bf16(acc[tm][tn * 2 + 0], a[tm], bb[tn][0], bb[tn][2]);
                    mma_bf16(acc[tm][tn * 2 + 1], a[tm], bb[tn][1], bb[tn][3]);
                }
        }
        __syncthreads();
    }

    // epilogue: bf16 hi/lo, q scaled x16
    __nv_bfloat16* __restrict__ outh = g_h[z];
    __nv_bfloat16* __restrict__ outl = g_l[z];
    const float sc = (z == 0) ? 16.0f : 1.0f;
    const int gr = lane >> 2;
    const int gc = lane & 3;
    #pragma unroll
    for (int tm = 0; tm < 2; tm++) {
        #pragma unroll
        for (int j = 0; j < 8; j++) {
            int r0g = m0 + wm * 32 + tm * 16 + gr;
            int col = n0 + wn * 64 + j * 8 + gc * 2;
            float v0 = acc[tm][j][0] * sc, v1 = acc[tm][j][1] * sc;
            float v2 = acc[tm][j][2] * sc, v3 = acc[tm][j][3] * sc;
            uint32_t h01 = pack_bf16(v0, v1);
            uint32_t h23 = pack_bf16(v2, v3);
            float h0 = __bfloat162float(__float2bfloat16(v0));
            float h1 = __bfloat162float(__float2bfloat16(v1));
            float h2 = __bfloat162float(__float2bfloat16(v2));
            float h3 = __bfloat162float(__float2bfloat16(v3));
            uint32_t l01 = pack_bf16(v0 - h0, v1 - h1);
            uint32_t l23 = pack_bf16(v2 - h2, v3 - h3);
            *(uint32_t*)&outh[(size_t)r0g * HDIM + col] = h01;
            *(uint32_t*)&outl[(size_t)r0g * HDIM + col] = l01;
            *(uint32_t*)&outh[(size_t)(r0g + 8) * HDIM + col] = h23;
            *(uint32_t*)&outl[(size_t)(r0g + 8) * HDIM + col] = l23;
        }
    }
}

// ============================================================================
// Flash attention via mma.sync bf16, full hi/lo split.
// QB=64 rows/CTA, KT=32 keys/tile, 256 threads (8 warps: 4M x 2N).
// grid = 256 CTAs (8 batches x 32 qblocks), heavy qb first.
// ============================================================================
// smem offsets (bytes)
#define AQH 0
#define AQL 32768
#define AKV0 65536            // per buffer 65536: KH,KL,VH,VL each 16384
#define APHI 196608           // P hi: 64 rows x 80 B
#define APLO 201728
#define ARED 206848           // redm 64*2 floats, then redl 64*2 floats
#define ATTN_SMEM_BYTES 207872

__global__ __launch_bounds__(256, 1) void attn_mma_kernel(float* __restrict__ out)
{
    extern __shared__ __align__(16) char as_[];
    const uint32_t sb = smem_u32(as_);
    float* redm = (float*)(as_ + ARED);
    float* redl = (float*)(as_ + ARED + 512);

    const int tid = threadIdx.x, lane = tid & 31, wid = tid >> 5;
    const int wm = wid & 3, wn = wid >> 2;
    const int bid = blockIdx.x;
    const int qb = 31 - (bid >> 3), b = bid & 7;
    const int q0 = qb * 64;
    const int nt = 2 * qb + 2;

    const __nv_bfloat16* __restrict__ qh = g_h[0] + ((size_t)b * TLEN + q0) * HDIM;
    const __nv_bfloat16* __restrict__ ql = g_l[0] + ((size_t)b * TLEN + q0) * HDIM;
    const __nv_bfloat16* __restrict__ kh = g_h[1] + (size_t)b * TLEN * HDIM;
    const __nv_bfloat16* __restrict__ kl = g_l[1] + (size_t)b * TLEN * HDIM;
    const __nv_bfloat16* __restrict__ vh = g_h[2] + (size_t)b * TLEN * HDIM;
    const __nv_bfloat16* __restrict__ vl = g_l[2] + (size_t)b * TLEN * HDIM;

    // Q load (2 planes x 64 rows x 32 chunks of 16B)
    #pragma unroll
    for (int it = 0; it < 8; it++) {
        int idx = it * 256 + tid;
        int row = idx >> 5, c = idx & 31;
        uint32_t sw = (uint32_t)(row * 512 + ((c << 4) ^ ((row & 7) << 4)));
        cp_async16(sb + AQH + sw, qh + (size_t)row * HDIM + c * 8);
        cp_async16(sb + AQL + sw, ql + (size_t)row * HDIM + c * 8);
    }
    auto load_kv = [&](int buf, int t) {
        int k0 = t * 32;
        uint32_t dst = sb + AKV0 + buf * 65536;
        const __nv_bfloat16* s[4] = {
            kh + (size_t)k0 * HDIM, kl + (size_t)k0 * HDIM,
            vh + (size_t)k0 * HDIM, vl + (size_t)k0 * HDIM };
        #pragma unroll
        for (int pl = 0; pl < 4; pl++) {
            #pragma unroll
            for (int it = 0; it < 4; it++) {
                int idx = it * 256 + tid;
                int row = idx >> 5, c = idx & 31;
                cp_async16(dst + pl * 16384 + row * 512 + ((c << 4) ^ ((row & 7) << 4)),
                           s[pl] + (size_t)row * HDIM + c * 8);
            }
        }
    };
    load_kv(0, 0); CP_COMMIT();          // group 0 also contains Q
    load_kv(1, 1); CP_COMMIT();

    float O[16][4];
    #pragma unroll
    for (int j = 0; j < 16; j++)
        #pragma unroll
        for (int e = 0; e < 4; e++) O[j][e] = 0.f;
    float m0v = -INFINITY, m1v = -INFINITY, l0 = 0.f, l1 = 0.f;

    const int r0 = lane >> 2;
    const int rowA = wm * 16 + r0;
    const uint32_t qoff = (uint32_t)((wm * 16 + (lane & 15)) * 512);
    const uint32_t qsw  = (uint32_t)((((wm * 16 + (lane & 15)) & 7)) << 4);
    const uint32_t koff = (uint32_t)((wn * 16 + (lane & 15)) * 512);
    const uint32_t ksw  = (uint32_t)((((wn * 16 + (lane & 15)) & 7)) << 4);
    const uint32_t poff = (uint32_t)((wm * 16 + (lane & 15)) * 80);

    for (int t = 0; t < nt; t++) {
        if (t + 1 < nt) { CP_WAIT1(); } else { CP_WAIT0(); }
        __syncthreads();
        const uint32_t KB  = sb + AKV0 + (t & 1) * 65536;
        const uint32_t KHb = KB, KLb = KB + 16384;
        const uint32_t VHb = KB + 32768, VLb = KB + 49152;

        // ---- S = Q K^T (16x16 per warp), 3-product split ----
        float s0[4] = {0.f, 0.f, 0.f, 0.f};
        float s1[4] = {0.f, 0.f, 0.f, 0.f};
        #pragma unroll
        for (int k16 = 0; k16 < 16; k16++) {
            uint32_t c = (uint32_t)((k16 * 2 + (lane >> 4)) << 4);
            uint32_t aH[4], aL[4], bH[4], bL[4];
            ldsm_x4(aH, sb + AQH + qoff + (c ^ qsw));
            ldsm_x4(aL, sb + AQL + qoff + (c ^ qsw));
            ldsm_x4(bH, KHb + koff + (c ^ ksw));
            ldsm_x4(bL, KLb + koff + (c ^ ksw));
            mma_bf16(s0, aH, bH[0], bH[2]); mma_bf16(s1, aH, bH[1], bH[3]);
            mma_bf16(s0, aL, bH[0], bH[2]); mma_bf16(s1, aL, bH[1], bH[3]);
            mma_bf16(s0, aH, bL[0], bL[2]); mma_bf16(s1, aH, bL[1], bL[3]);
        }

        // ---- causal mask (last 2 tiles only) ----
        const int k0g = t * 32;
        if (t >= nt - 2) {
            int growA = q0 + rowA;
            int colb  = k0g + wn * 16 + 2 * (lane & 3);
            if (colb     > growA)     s0[0] = -INFINITY;
            if (colb + 1 > growA)     s0[1] = -INFINITY;
            if (colb + 8 > growA)     s1[0] = -INFINITY;
            if (colb + 9 > growA)     s1[1] = -INFINITY;
            if (colb     > growA + 8) s0[2] = -INFINITY;
            if (colb + 1 > growA + 8) s0[3] = -INFINITY;
            if (colb + 8 > growA + 8) s1[2] = -INFINITY;
            if (colb + 9 > growA + 8) s1[3] = -INFINITY;
        }

        // ---- row max (quad shfl + cross-warp via smem) ----
        float mx0 = fmaxf(fmaxf(s0[0], s0[1]), fmaxf(s1[0], s1[1]));
        float mx1 = fmaxf(fmaxf(s0[2], s0[3]), fmaxf(s1[2], s1[3]));
        mx0 = fmaxf(mx0, __shfl_xor_sync(0xffffffffu, mx0, 1));
        mx0 = fmaxf(mx0, __shfl_xor_sync(0xffffffffu, mx0, 2));
        mx1 = fmaxf(mx1, __shfl_xor_sync(0xffffffffu, mx1, 1));
        mx1 = fmaxf(mx1, __shfl_xor_sync(0xffffffffu, mx1, 2));
        if ((lane & 3) == 0) {
            redm[rowA * 2 + wn] = mx0;
            redm[(rowA + 8) * 2 + wn] = mx1;
        }
        __syncthreads();
        float tm0 = fmaxf(redm[rowA * 2], redm[rowA * 2 + 1]);
        float tm1 = fmaxf(redm[(rowA + 8) * 2], redm[(rowA + 8) * 2 + 1]);
        float mn0 = fmaxf(m0v, tm0), mn1 = fmaxf(m1v, tm1);
        float al0 = __expf(m0v - mn0), al1 = __expf(m1v - mn1);

        s0[0] = __expf(s0[0] - mn0); s0[1] = __expf(s0[1] - mn0);
        s1[0] = __expf(s1[0] - mn0); s1[1] = __expf(s1[1] - mn0);
        s0[2] = __expf(s0[2] - mn1); s0[3] = __expf(s0[3] - mn1);
        s1[2] = __expf(s1[2] - mn1); s1[3] = __expf(s1[3] - mn1);

        float sm0 = s0[0] + s0[1] + s1[0] + s1[1];
        float sm1 = s0[2] + s0[3] + s1[2] + s1[3];
        sm0 += __shfl_xor_sync(0xffffffffu, sm0, 1);
        sm0 += __shfl_xor_sync(0xffffffffu, sm0, 2);
        sm1 += __shfl_xor_sync(0xffffffffu, sm1, 1);
        sm1 += __shfl_xor_sync(0xffffffffu, sm1, 2);
        if ((lane & 3) == 0) {
            redl[rowA * 2 + wn] = sm0;
            redl[(rowA + 8) * 2 + wn] = sm1;
        }

        // ---- pack P to bf16 hi/lo in smem ----
        {
            int colp = wn * 16 + 2 * (lane & 3);
            uint32_t rbase0 = sb + (uint32_t)(rowA * 80);
            uint32_t rbase1 = sb + (uint32_t)((rowA + 8) * 80);
            uint32_t h;
            h = pack_bf16(s0[0], s0[1]);
            *(uint32_t*)(as_ + (rbase0 - sb) + APHI + colp * 2) = h;
            *(uint32_t*)(as_ + (rbase0 - sb) + APLO + colp * 2) =
                pack_bf16(s0[0] - __bfloat162float(__float2bfloat16(s0[0])),
                          s0[1] - __bfloat162float(__float2bfloat16(s0[1])));
            h = pack_bf16(s1[0], s1[1]);
            *(uint32_t*)(as_ + (rbase0 - sb) + APHI + (colp + 8) * 2) = h;
            *(uint32_t*)(as_ + (rbase0 - sb) + APLO + (colp + 8) * 2) =
                pack_bf16(s1[0] - __bfloat162float(__float2bfloat16(s1[0])),
                          s1[1] - __bfloat162float(__float2bfloat16(s1[1])));
            h = pack_bf16(s0[2], s0[3]);
            *(uint32_t*)(as_ + (rbase1 - sb) + APHI + colp * 2) = h;
            *(uint32_t*)(as_ + (rbase1 - sb) + APLO + colp * 2) =
                pack_bf16(s0[2] - __bfloat162float(__float2bfloat16(s0[2])),
                          s0[3] - __bfloat162float(__float2bfloat16(s0[3])));
            h = pack_bf16(s1[2], s1[3]);
            *(uint32_t*)(as_ + (rbase1 - sb) + APHI + (colp + 8) * 2) = h;
            *(uint32_t*)(as_ + (rbase1 - sb) + APLO + (colp + 8) * 2) =
                pack_bf16(s1[2] - __bfloat162float(__float2bfloat16(s1[2])),
                          s1[3] - __bfloat162float(__float2bfloat16(s1[3])));
        }
        __syncthreads();

        // ---- l update + O rescale ----
        float ts0 = redl[rowA * 2] + redl[rowA * 2 + 1];
        float ts1 = redl[(rowA + 8) * 2] + redl[(rowA + 8) * 2 + 1];
        l0 = l0 * al0 + ts0;
        l1 = l1 * al1 + ts1;
        #pragma unroll
        for (int j = 0; j < 16; j++) {
            O[j][0] *= al0; O[j][1] *= al0;
            O[j][2] *= al1; O[j][3] *= al1;
        }

        // ---- O += P V (3-product split) ----
        #pragma unroll
        for (int ks = 0; ks < 2; ks++) {
            uint32_t pc = (uint32_t)((ks * 2 + (lane >> 4)) << 4);
            uint32_t pH[4], pL[4];
            ldsm_x4(pH, sb + APHI + poff + pc);
            ldsm_x4(pL, sb + APLO + poff + pc);
            int vrow = ks * 16 + (lane & 15);
            uint32_t voff = (uint32_t)(vrow * 512);
            uint32_t vsw  = (uint32_t)((vrow & 7) << 4);
            #pragma unroll
            for (int tn = 0; tn < 8; tn++) {
                uint32_t vc = (uint32_t)((wn * 16 + tn * 2 + (lane >> 4)) << 4);
                uint32_t vH[4], vL[4];
                ldsm_x4_t(vH, VHb + voff + (vc ^ vsw));
                ldsm_x4_t(vL, VLb + voff + (vc ^ vsw));
                mma_bf16(O[2 * tn],     pH, vH[0], vH[1]);
                mma_bf16(O[2 * tn + 1], pH, vH[2], vH[3]);
                mma_bf16(O[2 * tn],     pL, vH[0], vH[1]);
                mma_bf16(O[2 * tn + 1], pL, vH[2], vH[3]);
                mma_bf16(O[2 * tn],     pH, vL[0], vL[1]);
                mma_bf16(O[2 * tn + 1], pH, vL[2], vL[3]);
            }
        }
        m0v = mn0; m1v = mn1;
        __syncthreads();
        if (t + 2 < nt) { load_kv(t & 1, t + 2); CP_COMMIT(); }
    }

    // ---- epilogue ----
    float i0 = 1.f / l0, i1 = 1.f / l1;
    int gr0 = q0 + rowA;
    float* __restrict__ ob = out + (size_t)b * TLEN * HDIM;
    #pragma unroll
    for (int j = 0; j < 16; j++) {
        int col = wn * 128 + j * 8 + 2 * (lane & 3);
        *(float2*)&ob[(size_t)gr0 * HDIM + col] =
            make_float2(O[j][0] * i0, O[j][1] * i0);
        *(float2*)&ob[(size_t)(gr0 + 8) * HDIM + col] =
            make_float2(O[j][2] * i1, O[j][3] * i1);
    }
}

// ============================================================================
// Launch
// ============================================================================
extern "C" void kernel_launch(void* const* d_in, const int* in_sizes, int n_in,
                              void* d_out, int out_size)
{
    const float* x  = (const float*)d_in[0];
    const float* Wq = (const float*)d_in[1];
    const float* Wk = (const float*)d_in[2];
    const float* Wv = (const float*)d_in[3];
    float* out = (float*)d_out;
    (void)in_sizes; (void)n_in; (void)out_size;

    split_x_kernel<<<(size_t)MTOT * CDIM / (256 * 4), 256>>>(x);
    split_w_kernel<<<3 * CDIM * HDIM / 256, 256>>>(Wq, Wk, Wv);

    cudaFuncSetAttribute(proj_mma_kernel,
                         cudaFuncAttributeMaxDynamicSharedMemorySize,
                         PROJ_SMEM_BYTES);
    dim3 pgrid(MTOT / PM, HDIM / PN, 3);
    proj_mma_kernel<<<pgrid, 256, PROJ_SMEM_BYTES>>>();

    cudaFuncSetAttribute(attn_mma_kernel,
                         cudaFuncAttributeMaxDynamicSharedMemorySize,
                         ATTN_SMEM_BYTES);
    attn_mma_kernel<<<256, 256, ATTN_SMEM_BYTES>>>(out);
}